// round 5
// baseline (speedup 1.0000x reference)
#include <cuda_runtime.h>
#include <math.h>

// Shapes (fixed by the problem)
#define BWIN 256      // B_
#define NTOK 343      // N = 7*7*7
#define CH   384      // C
#define NH   12       // heads
#define HD   32       // head dim
#define KV2  768      // 2*C
#define NMASK 64      // nW
#define MROWS 87808   // BWIN*NTOK  (= 128*686)

// Scratch (device globals -- no cudaMalloc allowed)
__device__ float g_kv[BWIN * NTOK * KV2];     // kv projection output [b][n][768]
__device__ float g_attn[BWIN * NTOK * CH];    // attention output     [b][n][384]

// ---------------------------------------------------------------------------
// Packed f32x2 helpers (Blackwell FFMA2 — 2 fp32 FMAs per fma-pipe slot)
// ---------------------------------------------------------------------------
static __device__ __forceinline__ unsigned long long pk2(float a, float b) {
    unsigned long long v;
    asm("mov.b64 %0, {%1, %2};" : "=l"(v) : "f"(a), "f"(b));
    return v;
}
static __device__ __forceinline__ float2 up2(unsigned long long v) {
    float2 r;
    asm("mov.b64 {%0, %1}, %2;" : "=f"(r.x), "=f"(r.y) : "l"(v));
    return r;
}
static __device__ __forceinline__ void fma2(unsigned long long& d,
                                            unsigned long long a,
                                            unsigned long long b) {
    asm("fma.rn.f32x2 %0, %1, %2, %0;" : "+l"(d) : "l"(a), "l"(b));
}
static __device__ __forceinline__ void mul2(unsigned long long& d,
                                            unsigned long long a) {
    asm("mul.rn.f32x2 %0, %0, %1;" : "+l"(d) : "l"(a));
}

// ---------------------------------------------------------------------------
// SGEMM: C[M,Nc] = (A (+A2)) [M,K] @ B[K,Nc] + bias[Nc]
// BM=128 BN=128 BK=8, TM=TN=8, 256 threads, f32x2 packed inner product.
// ---------------------------------------------------------------------------
template <bool ADD>
__global__ __launch_bounds__(256)
void sgemm128(const float* __restrict__ A, const float* __restrict__ A2,
              const float* __restrict__ B, const float* __restrict__ bias,
              float* __restrict__ C, int M, int Nc, int K)
{
    constexpr int BM = 128, BN = 128, BK = 8, TM = 8, TN = 8;
    __shared__ float As[BK * BM];   // transposed: As[k][m]
    __shared__ float Bs[BK * BN];   // Bs[k][n]

    const int cRow = blockIdx.y;
    const int cCol = blockIdx.x;
    const int tid  = threadIdx.x;
    const int tCol = tid % (BN / TN);   // 0..15
    const int tRow = tid / (BN / TN);   // 0..15

    const float* Ab  = A  + (size_t)cRow * BM * K;
    const float* A2b = ADD ? (A2 + (size_t)cRow * BM * K) : nullptr;
    const float* Bb  = B  + cCol * BN;
    float*       Cb  = C  + (size_t)cRow * BM * Nc + cCol * BN;

    const int aRow = tid >> 1;          // 0..127
    const int aCol = (tid & 1) * 4;     // 0 or 4
    const int bRow = tid >> 5;          // 0..7
    const int bCol = (tid & 31) * 4;    // 0..124

    // acc2[i2][j] holds (acc[2*i2][j], acc[2*i2+1][j]) packed
    unsigned long long acc2[TM / 2][TN];
    #pragma unroll
    for (int i = 0; i < TM / 2; i++)
        #pragma unroll
        for (int j = 0; j < TN; j++) acc2[i][j] = 0ull;

    for (int k0 = 0; k0 < K; k0 += BK) {
        float4 av = *(const float4*)(Ab + (size_t)aRow * K + k0 + aCol);
        if (ADD) {
            float4 a2 = *(const float4*)(A2b + (size_t)aRow * K + k0 + aCol);
            av.x += a2.x; av.y += a2.y; av.z += a2.z; av.w += a2.w;
        }
        As[(aCol + 0) * BM + aRow] = av.x;
        As[(aCol + 1) * BM + aRow] = av.y;
        As[(aCol + 2) * BM + aRow] = av.z;
        As[(aCol + 3) * BM + aRow] = av.w;

        float4 bv = *(const float4*)(Bb + (size_t)(k0 + bRow) * Nc + bCol);
        *(float4*)(Bs + bRow * BN + bCol) = bv;

        __syncthreads();

        #pragma unroll
        for (int kk = 0; kk < BK; kk++) {
            float4 m0 = *(const float4*)(&As[kk * BM + tRow * TM]);
            float4 m1 = *(const float4*)(&As[kk * BM + tRow * TM + 4]);
            unsigned long long am0 = pk2(m0.x, m0.y);
            unsigned long long am1 = pk2(m0.z, m0.w);
            unsigned long long am2 = pk2(m1.x, m1.y);
            unsigned long long am3 = pk2(m1.z, m1.w);

            float4 n0 = *(const float4*)(&Bs[kk * BN + tCol * TN]);
            float4 n1 = *(const float4*)(&Bs[kk * BN + tCol * TN + 4]);
            float rN[TN];
            rN[0]=n0.x; rN[1]=n0.y; rN[2]=n0.z; rN[3]=n0.w;
            rN[4]=n1.x; rN[5]=n1.y; rN[6]=n1.z; rN[7]=n1.w;

            #pragma unroll
            for (int j = 0; j < TN; j++) {
                unsigned long long bb = pk2(rN[j], rN[j]);
                fma2(acc2[0][j], am0, bb);
                fma2(acc2[1][j], am1, bb);
                fma2(acc2[2][j], am2, bb);
                fma2(acc2[3][j], am3, bb);
            }
        }
        __syncthreads();
    }

    // epilogue with bias
    const float* brow = bias + cCol * BN + tCol * TN;
    float bb[TN];
    #pragma unroll
    for (int j = 0; j < TN; j++) bb[j] = brow[j];

    #pragma unroll
    for (int i2 = 0; i2 < TM / 2; i2++) {
        float rlo[TN], rhi[TN];
        #pragma unroll
        for (int j = 0; j < TN; j++) {
            float2 v = up2(acc2[i2][j]);
            rlo[j] = v.x + bb[j];
            rhi[j] = v.y + bb[j];
        }
        float* c0 = Cb + (size_t)(tRow * TM + 2 * i2) * Nc + tCol * TN;
        float* c1 = c0 + Nc;
        #pragma unroll
        for (int j = 0; j < TN; j += 4) {
            *(float4*)(c0 + j) = make_float4(rlo[j], rlo[j+1], rlo[j+2], rlo[j+3]);
            *(float4*)(c1 + j) = make_float4(rhi[j], rhi[j+1], rhi[j+2], rhi[j+3]);
        }
    }
}

// ---------------------------------------------------------------------------
// Fused window attention kernel: one CTA per (head, window-batch).
// f32x2 packed dot + PV accumulate; online softmax; mask prefetch.
// ---------------------------------------------------------------------------
__global__ __launch_bounds__(352, 2)
void attn_kernel(const float* __restrict__ xup,
                 const float* __restrict__ mask,
                 const float* __restrict__ lscale,
                 const float* __restrict__ rpb)
{
    const int h = blockIdx.x;
    const int b = blockIdx.y;

    extern __shared__ float sm[];
    float* kn   = sm;                 // 343*32 normalized K
    float* vv   = sm + NTOK * HD;     // 343*32 V
    float* btab = sm + 2 * NTOK * HD; // 412 floats (409 used)
    int*   code = (int*)(sm + 2 * NTOK * HD + 412); // 343 ints

    const float* kvb = g_kv + (size_t)b * NTOK * KV2;

    // Load K (normalize) and V into SMEM; compute position codes.
    for (int r = threadIdx.x; r < NTOK; r += 352) {
        const float4* ks = (const float4*)(kvb + (size_t)r * KV2 + h * HD);
        const float4* vs = (const float4*)(kvb + (size_t)r * KV2 + CH + h * HD);
        float4 kr[8];
        float ss = 0.f;
        #pragma unroll
        for (int j = 0; j < 8; j++) {
            kr[j] = ks[j];
            ss += kr[j].x * kr[j].x + kr[j].y * kr[j].y
                + kr[j].z * kr[j].z + kr[j].w * kr[j].w;
        }
        float inv = 1.f / fmaxf(sqrtf(ss), 1e-12f);
        float4* kd = (float4*)(kn + r * HD);
        float4* vd = (float4*)(vv + r * HD);
        #pragma unroll
        for (int j = 0; j < 8; j++) {
            float4 x = kr[j];
            x.x *= inv; x.y *= inv; x.z *= inv; x.w *= inv;
            kd[j] = x;
            vd[j] = vs[j];
        }
        int s = r / 49;
        int rem = r - s * 49;
        int hh = rem / 7;
        int w = rem - hh * 7;
        code[r] = s * 20 + hh * 13 + w;   // idx(n,m) = code[n]-code[m]+204 in [0,408]
    }
    for (int i = threadIdx.x; i < 409; i += 352)
        btab[i] = rpb[(size_t)i * NH + h];
    __syncthreads();

    const int n = threadIdx.x;
    if (n >= NTOK) return;

    // Load q row, fold normalization + logit scale into it; pack pairs.
    unsigned long long qp[16];
    {
        const float4* qs = (const float4*)(xup + ((size_t)b * NTOK + n) * CH + h * HD);
        float4 q[8];
        float ss = 0.f;
        #pragma unroll
        for (int j = 0; j < 8; j++) {
            q[j] = qs[j];
            ss += q[j].x * q[j].x + q[j].y * q[j].y + q[j].z * q[j].z + q[j].w * q[j].w;
        }
        float sc = __expf(fminf(lscale[h], 4.6051702f));   // min(logit_scale, ln 100)
        float qm = sc / fmaxf(sqrtf(ss), 1e-12f);
        #pragma unroll
        for (int j = 0; j < 8; j++) {
            qp[2 * j + 0] = pk2(q[j].x * qm, q[j].y * qm);
            qp[2 * j + 1] = pk2(q[j].z * qm, q[j].w * qm);
        }
    }

    const float* mrow = mask + ((size_t)(b & 63) * NTOK + n) * NTOK;
    const int cn = code[n] + 204;

    float Mx = -1e30f, L = 0.f;
    unsigned long long acc2[16];
    #pragma unroll
    for (int j = 0; j < 16; j++) acc2[j] = 0ull;

    float mv = __ldg(mrow);   // prefetched mask value for current m

    for (int m = 0; m < NTOK; m++) {
        // prefetch next mask value (hides L2 latency); m=NTOK-1 re-reads last
        const int mnext = (m + 1 < NTOK) ? m + 1 : m;
        float mv_next = __ldg(mrow + mnext);

        const unsigned long long* kr = (const unsigned long long*)(kn + m * HD);
        // 4 independent packed dot chains over 16 pairs
        unsigned long long d0 = 0ull, d1 = 0ull, d2 = 0ull, d3 = 0ull;
        #pragma unroll
        for (int t = 0; t < 4; t++) {
            fma2(d0, qp[4 * t + 0], kr[4 * t + 0]);
            fma2(d1, qp[4 * t + 1], kr[4 * t + 1]);
            fma2(d2, qp[4 * t + 2], kr[4 * t + 2]);
            fma2(d3, qp[4 * t + 3], kr[4 * t + 3]);
        }
        float2 f0 = up2(d0), f1 = up2(d1), f2 = up2(d2), f3 = up2(d3);
        float s = ((f0.x + f0.y) + (f1.x + f1.y)) + ((f2.x + f2.y) + (f3.x + f3.y));
        s += btab[cn - code[m]] + mv;
        mv = mv_next;

        float Mn = fmaxf(Mx, s);
        float p = __expf(s - Mn);
        if (Mn > Mx) {
            float c = __expf(Mx - Mn);
            L = L * c + p;
            unsigned long long cd = pk2(c, c);
            #pragma unroll
            for (int j = 0; j < 16; j++) mul2(acc2[j], cd);
            Mx = Mn;
        } else {
            L += p;
        }
        const unsigned long long* vr = (const unsigned long long*)(vv + m * HD);
        unsigned long long pd = pk2(p, p);
        #pragma unroll
        for (int j = 0; j < 16; j++) fma2(acc2[j], pd, vr[j]);
    }

    float invL = 1.f / L;
    unsigned long long iv = pk2(invL, invL);
    ulonglong2* od = (ulonglong2*)(g_attn + ((size_t)b * NTOK + n) * CH + h * HD);
    #pragma unroll
    for (int j = 0; j < 8; j++) {
        mul2(acc2[2 * j + 0], iv);
        mul2(acc2[2 * j + 1], iv);
        ulonglong2 o;
        o.x = acc2[2 * j + 0];
        o.y = acc2[2 * j + 1];
        od[j] = o;
    }
}

// ---------------------------------------------------------------------------
// Launch
// ---------------------------------------------------------------------------
extern "C" void kernel_launch(void* const* d_in, const int* in_sizes, int n_in,
                              void* d_out, int out_size)
{
    const float* skip   = (const float*)d_in[0];
    const float* x_up   = (const float*)d_in[1];
    const float* pos    = (const float*)d_in[2];
    const float* mask   = (const float*)d_in[3];
    const float* kv_w   = (const float*)d_in[4];
    const float* kv_b   = (const float*)d_in[5];
    const float* proj_w = (const float*)d_in[6];
    const float* proj_b = (const float*)d_in[7];
    const float* lsc    = (const float*)d_in[8];
    const float* rpb    = (const float*)d_in[9];
    float* out = (float*)d_out;

    void* kvp = nullptr;
    void* atp = nullptr;
    cudaGetSymbolAddress(&kvp, g_kv);
    cudaGetSymbolAddress(&atp, g_attn);
    float* kv_scratch   = (float*)kvp;
    float* attn_scratch = (float*)atp;

    const int smem_attn = (2 * NTOK * HD + 412) * 4 + NTOK * 4;  // ~90.8 KB
    cudaFuncSetAttribute(attn_kernel, cudaFuncAttributeMaxDynamicSharedMemorySize, smem_attn);

    // 1) KV projection: [87808,384] x [384,768] + bias
    sgemm128<false><<<dim3(KV2 / 128, MROWS / 128), 256>>>(
        skip, nullptr, kv_w, kv_b, kv_scratch, MROWS, KV2, CH);

    // 2) Fused cosine window attention (per head x window-batch)
    attn_kernel<<<dim3(NH, BWIN), 352, smem_attn>>>(x_up, mask, lsc, rpb);

    // 3) Output projection with fused (+pos_embed): [87808,384] x [384,384] + bias
    sgemm128<true><<<dim3(CH / 128, MROWS / 128), 256>>>(
        attn_scratch, pos, proj_w, proj_b, out, MROWS, CH, CH);
}

// round 6
// speedup vs baseline: 1.0573x; 1.0573x over previous
#include <cuda_runtime.h>
#include <math.h>
#include <stdint.h>

// Shapes (fixed by the problem)
#define BWIN 256      // B_
#define NTOK 343      // N = 7*7*7
#define CH   384      // C
#define NH   12       // heads
#define HD   32       // head dim
#define KV2  768      // 2*C
#define NMASK 64      // nW
#define MROWS 87808   // BWIN*NTOK  (= 128*686)

// Scratch (device globals -- no cudaMalloc allowed)
__device__ float g_kv[BWIN * NTOK * KV2];     // kv projection output [b][n][768]
__device__ float g_attn[BWIN * NTOK * CH];    // attention output     [b][n][384]

// ---------------------------------------------------------------------------
// TF32 helpers: split fp32 x into (hi, lo) tf32 values; 3xTF32 mma trick.
// ---------------------------------------------------------------------------
static __device__ __forceinline__ float2 split_tf32(float x) {
    uint32_t h;
    asm("cvt.rna.tf32.f32 %0, %1;" : "=r"(h) : "f"(x));
    float hf = __uint_as_float(h);
    float lo = x - hf;
    uint32_t l;
    asm("cvt.rna.tf32.f32 %0, %1;" : "=r"(l) : "f"(lo));
    return make_float2(hf, __uint_as_float(l));
}

static __device__ __forceinline__ void mma_tf32(float* c,
                                                float a0, float a1, float a2, float a3,
                                                float b0, float b1) {
    uint32_t A0 = __float_as_uint(a0), A1 = __float_as_uint(a1);
    uint32_t A2 = __float_as_uint(a2), A3 = __float_as_uint(a3);
    uint32_t B0 = __float_as_uint(b0), B1 = __float_as_uint(b1);
    asm volatile(
        "mma.sync.aligned.m16n8k8.row.col.f32.tf32.tf32.f32 "
        "{%0,%1,%2,%3}, {%4,%5,%6,%7}, {%8,%9}, {%0,%1,%2,%3};\n"
        : "+f"(c[0]), "+f"(c[1]), "+f"(c[2]), "+f"(c[3])
        : "r"(A0), "r"(A1), "r"(A2), "r"(A3), "r"(B0), "r"(B1));
}

// ---------------------------------------------------------------------------
// Tensor-core SGEMM (3xTF32, fp32-accurate):
//   C[M,Nc] = (A (+A2)) [M,K] @ B[K,Nc] + bias[Nc]
// BM=128 BN=128 BK=16. 256 threads = 8 warps as 4(m) x 2(n); warp tile 32x64.
// A/B staged in SMEM as float2(hi,lo) tf32 pairs.
// ---------------------------------------------------------------------------
#define APITCH 18    // float2 pitch for As rows (16 k + 2 pad)
#define BPITCH 132   // float2 pitch for Bs rows (128 n + 4 pad)

template <bool ADD>
__global__ __launch_bounds__(256, 2)
void sgemm_tc(const float* __restrict__ A, const float* __restrict__ A2,
              const float* __restrict__ B, const float* __restrict__ bias,
              float* __restrict__ C, int M, int Nc, int K)
{
    __shared__ float2 As[128 * APITCH];  // [m][k] (hi,lo)
    __shared__ float2 Bs[16 * BPITCH];   // [k][n] (hi,lo)

    const int tid  = threadIdx.x;
    const int wid  = tid >> 5;
    const int lane = tid & 31;
    const int g    = lane >> 2;      // groupID (0..7)
    const int t    = lane & 3;       // threadID_in_group (0..3)
    const int wm   = (wid >> 1) * 32;  // warp m offset in tile
    const int wn   = (wid & 1) * 64;   // warp n offset in tile

    const int cRow = blockIdx.y;
    const int cCol = blockIdx.x;

    const float* Ab  = A + (size_t)cRow * 128 * K;
    const float* A2b = ADD ? (A2 + (size_t)cRow * 128 * K) : nullptr;

    // A staging indices: each thread loads one row, 8 k values
    const int arow = tid >> 1;
    const int akk  = (tid & 1) * 8;
    // B staging indices: each thread loads one k row, 8 n values
    const int bkr = tid >> 4;
    const int bnn = (tid & 15) * 8;

    float acc[2][8][4];
    #pragma unroll
    for (int mf = 0; mf < 2; mf++)
        #pragma unroll
        for (int nf = 0; nf < 8; nf++)
            #pragma unroll
            for (int r = 0; r < 4; r++) acc[mf][nf][r] = 0.f;

    for (int k0 = 0; k0 < K; k0 += 16) {
        // ---- stage A tile (convert to hi/lo tf32 pairs) ----
        {
            float4 v0 = *(const float4*)(Ab + (size_t)arow * K + k0 + akk);
            float4 v1 = *(const float4*)(Ab + (size_t)arow * K + k0 + akk + 4);
            if (ADD) {
                float4 w0 = *(const float4*)(A2b + (size_t)arow * K + k0 + akk);
                float4 w1 = *(const float4*)(A2b + (size_t)arow * K + k0 + akk + 4);
                v0.x += w0.x; v0.y += w0.y; v0.z += w0.z; v0.w += w0.w;
                v1.x += w1.x; v1.y += w1.y; v1.z += w1.z; v1.w += w1.w;
            }
            float2* dst = &As[arow * APITCH + akk];
            dst[0] = split_tf32(v0.x); dst[1] = split_tf32(v0.y);
            dst[2] = split_tf32(v0.z); dst[3] = split_tf32(v0.w);
            dst[4] = split_tf32(v1.x); dst[5] = split_tf32(v1.y);
            dst[6] = split_tf32(v1.z); dst[7] = split_tf32(v1.w);
        }
        // ---- stage B tile ----
        {
            const float* Bp = B + (size_t)(k0 + bkr) * Nc + cCol * 128 + bnn;
            float4 v0 = *(const float4*)(Bp);
            float4 v1 = *(const float4*)(Bp + 4);
            float2* dst = &Bs[bkr * BPITCH + bnn];
            dst[0] = split_tf32(v0.x); dst[1] = split_tf32(v0.y);
            dst[2] = split_tf32(v0.z); dst[3] = split_tf32(v0.w);
            dst[4] = split_tf32(v1.x); dst[5] = split_tf32(v1.y);
            dst[6] = split_tf32(v1.z); dst[7] = split_tf32(v1.w);
        }
        __syncthreads();

        #pragma unroll
        for (int ks = 0; ks < 2; ks++) {
            const int kb = ks * 8;
            // A fragments for both m-frags: (hi,lo) per reg
            float2 af[2][4];
            #pragma unroll
            for (int mf = 0; mf < 2; mf++) {
                const int mb = wm + mf * 16;
                af[mf][0] = As[(mb + g)     * APITCH + kb + t];
                af[mf][1] = As[(mb + g + 8) * APITCH + kb + t];
                af[mf][2] = As[(mb + g)     * APITCH + kb + t + 4];
                af[mf][3] = As[(mb + g + 8) * APITCH + kb + t + 4];
            }
            #pragma unroll
            for (int nf = 0; nf < 8; nf++) {
                float2 b0 = Bs[(kb + t)     * BPITCH + wn + nf * 8 + g];
                float2 b1 = Bs[(kb + t + 4) * BPITCH + wn + nf * 8 + g];
                #pragma unroll
                for (int mf = 0; mf < 2; mf++) {
                    float* c = acc[mf][nf];
                    // 3xTF32: Ah*Bh + Ah*Bl + Al*Bh
                    mma_tf32(c, af[mf][0].x, af[mf][1].x, af[mf][2].x, af[mf][3].x, b0.x, b1.x);
                    mma_tf32(c, af[mf][0].x, af[mf][1].x, af[mf][2].x, af[mf][3].x, b0.y, b1.y);
                    mma_tf32(c, af[mf][0].y, af[mf][1].y, af[mf][2].y, af[mf][3].y, b0.x, b1.x);
                }
            }
        }
        __syncthreads();
    }

    // ---- epilogue: bias add + store ----
    #pragma unroll
    for (int mf = 0; mf < 2; mf++) {
        const int row0 = cRow * 128 + wm + mf * 16 + g;
        #pragma unroll
        for (int nf = 0; nf < 8; nf++) {
            const int col = cCol * 128 + wn + nf * 8 + t * 2;
            float2 bb = *(const float2*)(bias + col);
            float2 o0, o1;
            o0.x = acc[mf][nf][0] + bb.x;
            o0.y = acc[mf][nf][1] + bb.y;
            o1.x = acc[mf][nf][2] + bb.x;
            o1.y = acc[mf][nf][3] + bb.y;
            *(float2*)(C + (size_t)row0 * Nc + col)       = o0;
            *(float2*)(C + (size_t)(row0 + 8) * Nc + col) = o1;
        }
    }
}

// ---------------------------------------------------------------------------
// Fused window attention kernel (R2 form): one CTA per (head, window-batch).
// K/V + bias table in SMEM; q normalized+scaled in registers; online softmax.
// ---------------------------------------------------------------------------
__global__ __launch_bounds__(352, 2)
void attn_kernel(const float* __restrict__ xup,
                 const float* __restrict__ mask,
                 const float* __restrict__ lscale,
                 const float* __restrict__ rpb)
{
    const int h = blockIdx.x;
    const int b = blockIdx.y;

    extern __shared__ float sm[];
    float* kn   = sm;                 // 343*32 normalized K
    float* vv   = sm + NTOK * HD;     // 343*32 V
    float* btab = sm + 2 * NTOK * HD; // 412 floats (409 used)
    int*   code = (int*)(sm + 2 * NTOK * HD + 412); // 343 ints

    const float* kvb = g_kv + (size_t)b * NTOK * KV2;

    for (int r = threadIdx.x; r < NTOK; r += 352) {
        const float4* ks = (const float4*)(kvb + (size_t)r * KV2 + h * HD);
        const float4* vs = (const float4*)(kvb + (size_t)r * KV2 + CH + h * HD);
        float4 kr[8];
        float ss = 0.f;
        #pragma unroll
        for (int j = 0; j < 8; j++) {
            kr[j] = ks[j];
            ss += kr[j].x * kr[j].x + kr[j].y * kr[j].y
                + kr[j].z * kr[j].z + kr[j].w * kr[j].w;
        }
        float inv = 1.f / fmaxf(sqrtf(ss), 1e-12f);
        float4* kd = (float4*)(kn + r * HD);
        float4* vd = (float4*)(vv + r * HD);
        #pragma unroll
        for (int j = 0; j < 8; j++) {
            float4 x = kr[j];
            x.x *= inv; x.y *= inv; x.z *= inv; x.w *= inv;
            kd[j] = x;
            vd[j] = vs[j];
        }
        int s = r / 49;
        int rem = r - s * 49;
        int hh = rem / 7;
        int w = rem - hh * 7;
        code[r] = s * 20 + hh * 13 + w;   // idx(n,m) = code[n]-code[m]+204 in [0,408]
    }
    for (int i = threadIdx.x; i < 409; i += 352)
        btab[i] = rpb[(size_t)i * NH + h];
    __syncthreads();

    const int n = threadIdx.x;
    if (n >= NTOK) return;

    float4 q[8];
    {
        const float4* qs = (const float4*)(xup + ((size_t)b * NTOK + n) * CH + h * HD);
        float ss = 0.f;
        #pragma unroll
        for (int j = 0; j < 8; j++) {
            q[j] = qs[j];
            ss += q[j].x * q[j].x + q[j].y * q[j].y + q[j].z * q[j].z + q[j].w * q[j].w;
        }
        float sc = __expf(fminf(lscale[h], 4.6051702f));   // min(logit_scale, ln 100)
        float qm = sc / fmaxf(sqrtf(ss), 1e-12f);
        #pragma unroll
        for (int j = 0; j < 8; j++) {
            q[j].x *= qm; q[j].y *= qm; q[j].z *= qm; q[j].w *= qm;
        }
    }

    const float* mrow = mask + ((size_t)(b & 63) * NTOK + n) * NTOK;
    const int cn = code[n] + 204;

    float Mx = -1e30f, L = 0.f;
    float4 acc[8];
    #pragma unroll
    for (int j = 0; j < 8; j++) acc[j] = make_float4(0.f, 0.f, 0.f, 0.f);

    for (int m = 0; m < NTOK; m++) {
        const float4* kr = (const float4*)(kn + m * HD);
        float d0 = 0.f, d1 = 0.f, d2 = 0.f, d3 = 0.f;
        #pragma unroll
        for (int j = 0; j < 8; j += 4) {
            float4 k0 = kr[j], k1 = kr[j + 1], k2 = kr[j + 2], k3 = kr[j + 3];
            d0 += q[j].x   * k0.x + q[j].y   * k0.y + q[j].z   * k0.z + q[j].w   * k0.w;
            d1 += q[j+1].x * k1.x + q[j+1].y * k1.y + q[j+1].z * k1.z + q[j+1].w * k1.w;
            d2 += q[j+2].x * k2.x + q[j+2].y * k2.y + q[j+2].z * k2.z + q[j+2].w * k2.w;
            d3 += q[j+3].x * k3.x + q[j+3].y * k3.y + q[j+3].z * k3.z + q[j+3].w * k3.w;
        }
        float s = (d0 + d1) + (d2 + d3);
        s += btab[cn - code[m]] + __ldg(mrow + m);

        float Mn = fmaxf(Mx, s);
        float p = __expf(s - Mn);
        if (Mn > Mx) {
            float c = __expf(Mx - Mn);
            L = L * c + p;
            #pragma unroll
            for (int j = 0; j < 8; j++) {
                acc[j].x *= c; acc[j].y *= c; acc[j].z *= c; acc[j].w *= c;
            }
            Mx = Mn;
        } else {
            L += p;
        }
        const float4* vr = (const float4*)(vv + m * HD);
        #pragma unroll
        for (int j = 0; j < 8; j++) {
            float4 vx = vr[j];
            acc[j].x += p * vx.x; acc[j].y += p * vx.y;
            acc[j].z += p * vx.z; acc[j].w += p * vx.w;
        }
    }

    float invL = 1.f / L;
    float4* od = (float4*)(g_attn + ((size_t)b * NTOK + n) * CH + h * HD);
    #pragma unroll
    for (int j = 0; j < 8; j++) {
        acc[j].x *= invL; acc[j].y *= invL; acc[j].z *= invL; acc[j].w *= invL;
        od[j] = acc[j];
    }
}

// ---------------------------------------------------------------------------
// Launch
// ---------------------------------------------------------------------------
extern "C" void kernel_launch(void* const* d_in, const int* in_sizes, int n_in,
                              void* d_out, int out_size)
{
    const float* skip   = (const float*)d_in[0];
    const float* x_up   = (const float*)d_in[1];
    const float* pos    = (const float*)d_in[2];
    const float* mask   = (const float*)d_in[3];
    const float* kv_w   = (const float*)d_in[4];
    const float* kv_b   = (const float*)d_in[5];
    const float* proj_w = (const float*)d_in[6];
    const float* proj_b = (const float*)d_in[7];
    const float* lsc    = (const float*)d_in[8];
    const float* rpb    = (const float*)d_in[9];
    float* out = (float*)d_out;

    void* kvp = nullptr;
    void* atp = nullptr;
    cudaGetSymbolAddress(&kvp, g_kv);
    cudaGetSymbolAddress(&atp, g_attn);
    float* kv_scratch   = (float*)kvp;
    float* attn_scratch = (float*)atp;

    const int smem_attn = (2 * NTOK * HD + 412) * 4 + NTOK * 4;  // ~90.8 KB
    cudaFuncSetAttribute(attn_kernel, cudaFuncAttributeMaxDynamicSharedMemorySize, smem_attn);

    // 1) KV projection: [87808,384] x [384,768] + bias  (3xTF32 tensor cores)
    sgemm_tc<false><<<dim3(KV2 / 128, MROWS / 128), 256>>>(
        skip, nullptr, kv_w, kv_b, kv_scratch, MROWS, KV2, CH);

    // 2) Fused cosine window attention (per head x window-batch)
    attn_kernel<<<dim3(NH, BWIN), 352, smem_attn>>>(x_up, mask, lsc, rpb);

    // 3) Output projection with fused (+pos_embed): [87808,384] x [384,384] + bias
    sgemm_tc<true><<<dim3(CH / 128, MROWS / 128), 256>>>(
        attn_scratch, pos, proj_w, proj_b, out, MROWS, CH, CH);
}